// round 13
// baseline (speedup 1.0000x reference)
#include <cuda_runtime.h>
#include <cstdint>

// RoIBridge round 13: TMA bulk-store path.
// R8-R12 plateau at ~4.45TB/s with no unit saturated -> hypothesis: per-SM
// STG outstanding-request capacity binds the write stream. Replace per-thread
// STG with cp.async.bulk (TMA) stores from smem staging tiles:
//  - 456 blocks x 512 thr (3/SM). smem: 57.6KB table + 2 x 8KB staging.
//  - tile = 8 rows = 8KB contiguous output = 512 float4 = 1 per thread
//  - warp-uniform obj/frac loads (32 lanes same row -> 1-sector broadcast),
//    software-pipelined across tiles
//  - conditional LDS gathers (half the rows are masked -> skip their LDS)
//  - fence.proxy.async + syncthreads + single-thread bulk store + commit;
//    wait_group.read 1 gates staging-buffer reuse (double buffer)

static constexpr int IMAGE_SIZE = 224;
static constexpr int ROWS = 2048 * 128;       // 262144
static constexpr int TABLE_F4 = 225 * 16;     // 3600 float4 = 57600 B
static constexpr int TILE_ROWS = 8;
static constexpr int NTILES = ROWS / TILE_ROWS;       // 32768
static constexpr int TILE_F4 = TILE_ROWS * 64;        // 512
static constexpr int TILE_BYTES = TILE_F4 * 16;       // 8192

__device__ __forceinline__ int clamp_idx(float f) {
    float x = fminf(fmaxf(f * (float)IMAGE_SIZE, 0.0f), (float)IMAGE_SIZE);
    return (int)x;   // trunc toward zero == astype(int32), x >= 0
}

extern __shared__ float4 smem_dyn[];
// layout: stage[2][512] float4 (16384 B), then table[3600] float4 (57600 B)

__global__ void __launch_bounds__(512, 3)
roibridge_kernel(const float4* __restrict__ frac4,   // [ROWS]
                 const int*    __restrict__ obj,     // [ROWS]
                 const float4* __restrict__ table4,  // [225*16]
                 float4*       __restrict__ out)     // [ROWS*64]
{
    float4* s_stage = smem_dyn;                 // [2][TILE_F4]
    float4* s_tab   = smem_dyn + 2 * TILE_F4;   // [TABLE_F4]

    // ---- stage table into shared memory (one-time per block) ----
    for (int i = threadIdx.x; i < TABLE_F4; i += blockDim.x)
        s_tab[i] = table4[i];
    __syncthreads();

    const int tid_in = threadIdx.x;
    const int rsub   = tid_in >> 6;      // row within tile 0..7
    const int d4     = tid_in & 63;      // float4 within row
    const int c      = d4 >> 4;          // coordinate 0..3
    const int dd     = d4 & 15;          // float4 lane within coord embedding

    uint32_t stage_addr0;
    asm("{ .reg .u64 t; cvta.to.shared.u64 t, %1; cvt.u32.u64 %0, t; }"
        : "=r"(stage_addr0) : "l"((void*)s_stage));

    const float4 z = make_float4(0.f, 0.f, 0.f, 0.f);

    // ---- prologue: scalar loads for first tile ----
    int t = blockIdx.x;
    int    o = 0;
    float4 f = z;
    if (t < NTILES) {
        int row = t * TILE_ROWS + rsub;
        o = __ldg(obj + row);
        f = __ldg(frac4 + row);
    }

    int it = 0;
    for (; t < NTILES; t += gridDim.x, ++it) {
        const int buf = it & 1;

        // ---- make staging buffer safe for reuse (<=1 unread group) ----
        if (tid_in == 0)
            asm volatile("cp.async.bulk.wait_group.read 1;" ::: "memory");
        __syncthreads();

        // ---- gather this thread's float4 (conditional on mask) ----
        float4 v = z;
        if (o == 1) {
            float fc = (c == 0) ? f.x : (c == 1) ? f.y : (c == 2) ? f.z : f.w;
            v = s_tab[clamp_idx(fc) * 16 + dd];
        }
        s_stage[buf * TILE_F4 + tid_in] = v;

        // ---- prefetch next tile's scalars (overlaps fence/bar/TMA) ----
        const int tn = t + gridDim.x;
        if (tn < NTILES) {
            int row = tn * TILE_ROWS + rsub;
            o = __ldg(obj + row);
            f = __ldg(frac4 + row);
        }

        // ---- order STS before async-proxy read, then bulk store ----
        asm volatile("fence.proxy.async.shared::cta;" ::: "memory");
        __syncthreads();
        if (tid_in == 0) {
            const float4* gdst = out + (size_t)t * TILE_F4;
            uint32_t saddr = stage_addr0 + buf * TILE_BYTES;
            asm volatile(
                "cp.async.bulk.global.shared::cta.bulk_group [%0], [%1], %2;"
                :: "l"(gdst), "r"(saddr), "r"((int)TILE_BYTES) : "memory");
            asm volatile("cp.async.bulk.commit_group;" ::: "memory");
        }
    }

    // ---- drain all outstanding bulk stores before exit ----
    if (tid_in == 0)
        asm volatile("cp.async.bulk.wait_group 0;" ::: "memory");
}

extern "C" void kernel_launch(void* const* d_in, const int* in_sizes, int n_in,
                              void* d_out, int out_size)
{
    const float4* frac4 = (const float4*)d_in[0];   // [2048,128,4] f32
    const int*    obj   = (const int*)d_in[1];      // [2048,128] i32
    const float4* table = (const float4*)d_in[2];   // [225,64] f32
    float4* out = (float4*)d_out;

    const int smem_bytes = (2 * TILE_F4 + TABLE_F4) * sizeof(float4); // 73984
    cudaFuncSetAttribute(roibridge_kernel,
                         cudaFuncAttributeMaxDynamicSharedMemorySize, smem_bytes);

    const int threads = 512;
    const int blocks = 152 * 3;   // 152 SMs, 3 blocks/SM

    roibridge_kernel<<<blocks, threads, smem_bytes>>>(frac4, obj, table, out);
}